// round 7
// baseline (speedup 1.0000x reference)
#include <cuda_runtime.h>
#include <cuda_bf16.h>
#include <cstdint>

#define BATCH 16384
#define DIM   128
#define NREL  500
#define MAXC  2048
#define ALPHA 0.001f

#define NW   8           // warps per block
#define KPB  272         // bytes per bf16 tile row (136 elems)
#define HP   132         // H row stride in floats

// device scratch
__device__ float g_acc[4];     // 0=sum h^2, 1=sum t^2, 2=sum ||R||^2*count, 3=sum sq err
__device__ int   g_cnt[NREL];
__device__ int   g_bucket[NREL * MAXC];
__device__ int   g_ready;      // bucket-producer arrival counter (blocks 0..127)
__device__ int   g_done;       // block completion counter

// ---- smem layout (bytes) ----
#define OFF_RHI 0
#define OFF_RLO (128 * KPB)                        // 34816
#define OFF_T   (2 * 128 * KPB)                    // 69632
#define T_WARP  (16 * KPB * 2)                     // 8704 (hi then lo)
#define OFF_H   (OFF_T + NW * T_WARP)              // 139264
#define H_WARP  (16 * HP * 4)                      // 8448
#define SMEM_TOTAL (OFF_H + NW * H_WARP)           // 206848

extern __shared__ char smem[];

__device__ __forceinline__ float warpSum(float v) {
#pragma unroll
    for (int o = 16; o > 0; o >>= 1) v += __shfl_xor_sync(0xffffffffu, v, o);
    return v;
}

__device__ __forceinline__ void split2(float x, float y,
                                       __nv_bfloat162& hi, __nv_bfloat162& lo) {
    hi = __floats2bfloat162_rn(x, y);
    lo = __floats2bfloat162_rn(x - __bfloat162float(hi.x),
                               y - __bfloat162float(hi.y));
}

__device__ __forceinline__ void mma_bf16(float& c0, float& c1, float& c2, float& c3,
                                         uint32_t a0, uint32_t a1, uint32_t a2, uint32_t a3,
                                         uint32_t b0, uint32_t b1) {
    asm volatile(
        "mma.sync.aligned.m16n8k16.row.col.f32.bf16.bf16.f32 "
        "{%0,%1,%2,%3}, {%4,%5,%6,%7}, {%8,%9}, {%0,%1,%2,%3};"
        : "+f"(c0), "+f"(c1), "+f"(c2), "+f"(c3)
        : "r"(a0), "r"(a1), "r"(a2), "r"(a3), "r"(b0), "r"(b1));
}

__global__ __launch_bounds__(256, 1) void rescal_fused(
    const int*   __restrict__ h_idx,
    const int*   __restrict__ r_idx,
    const int*   __restrict__ t_idx,
    const float* __restrict__ labels,
    const float* __restrict__ ent_w,
    const float* __restrict__ rel_w,
    float*       __restrict__ out)
{
    __shared__ float sH2, sT2, sE2, sR2;
    __shared__ int   sLast;

    const int tid  = threadIdx.x;
    const int lane = tid & 31;
    const int wid  = tid >> 5;
    const int rel  = blockIdx.x;

    char* Rhi = smem + OFF_RHI;
    char* Rlo = smem + OFF_RLO;
    char* Thi = smem + OFF_T + wid * T_WARP;
    char* Tlo = Thi + 16 * KPB;
    float* Hw = (float*)(smem + OFF_H + wid * H_WARP);

    if (tid == 0) { sH2 = 0.f; sT2 = 0.f; sE2 = 0.f; sR2 = 0.f; sLast = 0; }
    __syncthreads();

    // ---- Phase A: blocks 0..127 bucket 128 indices each (covers BATCH exactly) ----
    if (rel < 128) {
        if (tid < 128) {
            int i    = rel * 128 + tid;
            int rl   = r_idx[i];
            int slot = atomicAdd(&g_cnt[rl], 1);
            if (slot < MAXC) g_bucket[rl * MAXC + slot] = i;
            __threadfence();
        }
        __syncthreads();
        if (tid == 0) atomicAdd(&g_ready, 1);
    }

    // ---- Phase B: R [128x128] -> bf16 hi/lo tiles (256 threads, 16 iters); ||R||^2 ----
    const float4* Rg = (const float4*)rel_w + (size_t)rel * 4096;
    float r2 = 0.f;
#pragma unroll 4
    for (int it = 0; it < 16; it++) {
        int i   = it * 256 + tid;
        int row = i >> 5;
        int col = (i & 31) * 4;
        float4 v = Rg[i];
        r2 += v.x * v.x + v.y * v.y + v.z * v.z + v.w * v.w;
        __nv_bfloat162 h0, l0, h1, l1;
        split2(v.x, v.y, h0, l0);
        split2(v.z, v.w, h1, l1);
        char* ph = Rhi + row * KPB + col * 2;
        char* pl = Rlo + row * KPB + col * 2;
        *(__nv_bfloat162*)(ph)     = h0;
        *(__nv_bfloat162*)(ph + 4) = h1;
        *(__nv_bfloat162*)(pl)     = l0;
        *(__nv_bfloat162*)(pl + 4) = l1;
    }
    r2 = warpSum(r2);
    if (lane == 0) atomicAdd(&sR2, r2);

    // ---- Phase C: wait for all bucket producers, then read my bucket ----
    if (tid == 0) {
        volatile int* p = &g_ready;
        while (*p < 128) { }
        __threadfence();
    }
    __syncthreads();

    int count = g_cnt[rel];
    if (count > MAXC) count = MAXC;
    const int* bucket = g_bucket + (size_t)rel * MAXC;

    float h2 = 0.f, t2 = 0.f, sq = 0.f;
    const int gr  = lane >> 2;
    const int tig = lane & 3;

    // ---- Phase D: per-warp 16-row chunks, stride NW*16 = 128 ----
    for (int base = wid * 16; base < count; base += NW * 16) {
        const int ne = min(16, count - base);

        // gather: 2 lanes per row, 64 elements (16 float4) each half
        {
            const int r    = lane >> 1;
            const int half = lane & 1;
            if (r < ne) {
                int i = bucket[base + r];
                const float4* tv = (const float4*)(ent_w + (size_t)t_idx[i] * DIM) + half * 16;
                const float4* hv = (const float4*)(ent_w + (size_t)h_idx[i] * DIM) + half * 16;
                char*  pth = Thi + r * KPB + half * 64 * 2;
                char*  ptl = Tlo + r * KPB + half * 64 * 2;
                float* phh = Hw + r * HP + half * 64;
#pragma unroll 4
                for (int f = 0; f < 16; f++) {
                    float4 t4 = tv[f];
                    float4 h4 = hv[f];
                    t2 += t4.x * t4.x + t4.y * t4.y + t4.z * t4.z + t4.w * t4.w;
                    h2 += h4.x * h4.x + h4.y * h4.y + h4.z * h4.z + h4.w * h4.w;
                    __nv_bfloat162 a0, b0, a1, b1;
                    split2(t4.x, t4.y, a0, b0);
                    split2(t4.z, t4.w, a1, b1);
                    *(__nv_bfloat162*)(pth + f * 8)     = a0;
                    *(__nv_bfloat162*)(pth + f * 8 + 4) = a1;
                    *(__nv_bfloat162*)(ptl + f * 8)     = b0;
                    *(__nv_bfloat162*)(ptl + f * 8 + 4) = b1;
                    *(float4*)(phh + f * 4) = h4;
                }
            } else if (r < 16) {
                char* pth = Thi + r * KPB + half * 64 * 2;
                char* ptl = Tlo + r * KPB + half * 64 * 2;
#pragma unroll 4
                for (int f = 0; f < 16; f++) {
                    *(float2*)(pth + f * 8) = make_float2(0.f, 0.f);
                    *(float2*)(ptl + f * 8) = make_float2(0.f, 0.f);
                }
            }
        }
        __syncwarp();

        // Y = T . R^T via 3-term bf16-split HMMA
        float acc[64];
#pragma unroll
        for (int j = 0; j < 64; j++) acc[j] = 0.f;

#pragma unroll 2
        for (int kt = 0; kt < 8; kt++) {
            const int ka = kt * 16 + 2 * tig;
            uint32_t ah0 = *(const uint32_t*)(Thi + gr * KPB + ka * 2);
            uint32_t ah1 = *(const uint32_t*)(Thi + (gr + 8) * KPB + ka * 2);
            uint32_t ah2 = *(const uint32_t*)(Thi + gr * KPB + (ka + 8) * 2);
            uint32_t ah3 = *(const uint32_t*)(Thi + (gr + 8) * KPB + (ka + 8) * 2);
            uint32_t al0 = *(const uint32_t*)(Tlo + gr * KPB + ka * 2);
            uint32_t al1 = *(const uint32_t*)(Tlo + (gr + 8) * KPB + ka * 2);
            uint32_t al2 = *(const uint32_t*)(Tlo + gr * KPB + (ka + 8) * 2);
            uint32_t al3 = *(const uint32_t*)(Tlo + (gr + 8) * KPB + (ka + 8) * 2);
#pragma unroll
            for (int nt = 0; nt < 16; nt++) {
                const int n = nt * 8 + gr;
                uint32_t bh0 = *(const uint32_t*)(Rhi + n * KPB + ka * 2);
                uint32_t bh1 = *(const uint32_t*)(Rhi + n * KPB + (ka + 8) * 2);
                uint32_t bl0 = *(const uint32_t*)(Rlo + n * KPB + ka * 2);
                uint32_t bl1 = *(const uint32_t*)(Rlo + n * KPB + (ka + 8) * 2);
                float* c = acc + nt * 4;
                mma_bf16(c[0], c[1], c[2], c[3], ah0, ah1, ah2, ah3, bh0, bh1);
                mma_bf16(c[0], c[1], c[2], c[3], ah0, ah1, ah2, ah3, bl0, bl1);
                mma_bf16(c[0], c[1], c[2], c[3], al0, al1, al2, al3, bh0, bh1);
            }
        }

        // epilogue: score[m] = sum_n H[m][n] * Y[m][n]
        float s0 = 0.f, s1 = 0.f;
#pragma unroll
        for (int nt = 0; nt < 16; nt++) {
            const int cn = nt * 8 + 2 * tig;
            float2 hA = *(const float2*)(Hw + gr * HP + cn);
            float2 hB = *(const float2*)(Hw + (gr + 8) * HP + cn);
            s0 += hA.x * acc[nt * 4 + 0] + hA.y * acc[nt * 4 + 1];
            s1 += hB.x * acc[nt * 4 + 2] + hB.y * acc[nt * 4 + 3];
        }
        s0 += __shfl_xor_sync(0xffffffffu, s0, 1);
        s0 += __shfl_xor_sync(0xffffffffu, s0, 2);
        s1 += __shfl_xor_sync(0xffffffffu, s1, 1);
        s1 += __shfl_xor_sync(0xffffffffu, s1, 2);
        if (tig == 0) {
            if (gr < ne) {
                int i = bucket[base + gr];
                out[1 + i] = s0;
                float d = s0 - labels[i];
                sq += d * d;
            }
            if (gr + 8 < ne) {
                int i = bucket[base + gr + 8];
                out[1 + i] = s1;
                float d = s1 - labels[i];
                sq += d * d;
            }
        }
        __syncwarp();
    }

    // ---- Phase E: loss partials + last-block finalize & state reset ----
    h2 = warpSum(h2);
    t2 = warpSum(t2);
    sq = warpSum(sq);
    if (lane == 0) {
        atomicAdd(&sH2, h2);
        atomicAdd(&sT2, t2);
        atomicAdd(&sE2, sq);
    }
    __syncthreads();
    if (tid == 0) {
        atomicAdd(&g_acc[0], sH2);
        atomicAdd(&g_acc[1], sT2);
        atomicAdd(&g_acc[2], sR2 * (float)count);
        atomicAdd(&g_acc[3], sE2);
        __threadfence();
        int old = atomicAdd(&g_done, 1);
        if (old == NREL - 1) sLast = 1;
    }
    __syncthreads();

    if (sLast) {
        // all prior blocks' g_acc atomics are ordered before their g_done arrival
        for (int i = tid; i < NREL; i += 256) g_cnt[i] = 0;
        if (tid == 0) {
            __threadfence();
            const float invBD  = 1.0f / ((float)BATCH * (float)DIM);
            const float invBDD = 1.0f / ((float)BATCH * (float)DIM * (float)DIM);
            float norms = (g_acc[0] * invBD + g_acc[1] * invBD + g_acc[2] * invBDD)
                        * (1.0f / 3.0f);
            out[0] = g_acc[3] / (float)BATCH + ALPHA * norms;
            g_acc[0] = 0.f; g_acc[1] = 0.f; g_acc[2] = 0.f; g_acc[3] = 0.f;
            g_done  = 0;
            g_ready = 0;
        }
    }
}

extern "C" void kernel_launch(void* const* d_in, const int* in_sizes, int n_in,
                              void* d_out, int out_size)
{
    const int*   h_idx  = (const int*)d_in[0];
    const int*   r_idx  = (const int*)d_in[1];
    const int*   t_idx  = (const int*)d_in[2];
    const float* labels = (const float*)d_in[3];
    const float* ent_w  = (const float*)d_in[4];
    const float* rel_w  = (const float*)d_in[5];
    float*       out    = (float*)d_out;

    cudaFuncSetAttribute(rescal_fused,
                         cudaFuncAttributeMaxDynamicSharedMemorySize, SMEM_TOTAL);

    rescal_fused<<<NREL, 256, SMEM_TOTAL>>>(h_idx, r_idx, t_idx, labels,
                                            ent_w, rel_w, out);
}

// round 8
// speedup vs baseline: 1.4766x; 1.4766x over previous
#include <cuda_runtime.h>
#include <cuda_bf16.h>
#include <cstdint>

#define BATCH 16384
#define DIM   128
#define NREL  500
#define MAXC  2048
#define ALPHA 0.001f
#define KPB   272        // bytes per bf16 tile row (136 elems -> conflict-free)

// device scratch
__device__ float g_acc[4];     // 0=sum h^2, 1=sum t^2, 2=sum ||R||^2*count, 3=sum sq err
__device__ int   g_cnt[NREL];
__device__ int   g_bucket[NREL * MAXC];
__device__ int   g_ready;
__device__ int   g_done;

#define OFF_RLO    (128 * KPB)          // 34816
#define SMEM_TOTAL (2 * 128 * KPB)      // 69632 -> 3 CTAs/SM

extern __shared__ char smem[];

__device__ __forceinline__ float warpSum(float v) {
#pragma unroll
    for (int o = 16; o > 0; o >>= 1) v += __shfl_xor_sync(0xffffffffu, v, o);
    return v;
}

// split-convert 2 floats -> packed bf16x2 hi and lo (residual)
__device__ __forceinline__ void split_u32(float x, float y, uint32_t& hi, uint32_t& lo) {
    __nv_bfloat162 h = __floats2bfloat162_rn(x, y);
    __nv_bfloat162 l = __floats2bfloat162_rn(x - __bfloat162float(h.x),
                                             y - __bfloat162float(h.y));
    hi = *reinterpret_cast<uint32_t*>(&h);
    lo = *reinterpret_cast<uint32_t*>(&l);
}

__device__ __forceinline__ void mma_bf16(float& c0, float& c1, float& c2, float& c3,
                                         uint32_t a0, uint32_t a1, uint32_t a2, uint32_t a3,
                                         uint32_t b0, uint32_t b1) {
    asm volatile(
        "mma.sync.aligned.m16n8k16.row.col.f32.bf16.bf16.f32 "
        "{%0,%1,%2,%3}, {%4,%5,%6,%7}, {%8,%9}, {%0,%1,%2,%3};"
        : "+f"(c0), "+f"(c1), "+f"(c2), "+f"(c3)
        : "r"(a0), "r"(a1), "r"(a2), "r"(a3), "r"(b0), "r"(b1));
}

__global__ __launch_bounds__(128, 3) void rescal_fused(
    const int*   __restrict__ h_idx,
    const int*   __restrict__ r_idx,
    const int*   __restrict__ t_idx,
    const float* __restrict__ labels,
    const float* __restrict__ ent_w,
    const float* __restrict__ rel_w,
    float*       __restrict__ out)
{
    __shared__ float sH2, sT2, sE2, sR2;
    __shared__ int   sLast;

    const int tid  = threadIdx.x;
    const int lane = tid & 31;
    const int wid  = tid >> 5;
    const int rel  = blockIdx.x;

    char* Rhi = smem;
    char* Rlo = smem + OFF_RLO;

    if (tid == 0) { sH2 = 0.f; sT2 = 0.f; sE2 = 0.f; sR2 = 0.f; sLast = 0; }
    __syncthreads();

    // ---- Phase A: blocks 0..127 bucket 128 indices each (128*128 = BATCH) ----
    if (rel < 128) {
        int i    = rel * 128 + tid;
        int rl   = r_idx[i];
        int slot = atomicAdd(&g_cnt[rl], 1);
        if (slot < MAXC) g_bucket[rl * MAXC + slot] = i;
        __threadfence();
        __syncthreads();
        if (tid == 0) atomicAdd(&g_ready, 1);
    }

    // ---- Phase B: R [128x128] fp32 -> bf16 hi/lo smem tiles; ||R||^2 ----
    const float4* Rg = (const float4*)rel_w + (size_t)rel * 4096;
    float r2 = 0.f;
#pragma unroll 4
    for (int it = 0; it < 32; it++) {
        int i   = it * 128 + tid;
        int row = i >> 5;
        int col = (i & 31) * 4;
        float4 v = Rg[i];
        r2 += v.x * v.x + v.y * v.y + v.z * v.z + v.w * v.w;
        uint32_t h0, l0, h1, l1;
        split_u32(v.x, v.y, h0, l0);
        split_u32(v.z, v.w, h1, l1);
        *(uint2*)(Rhi + row * KPB + col * 2) = make_uint2(h0, h1);
        *(uint2*)(Rlo + row * KPB + col * 2) = make_uint2(l0, l1);
    }
    r2 = warpSum(r2);
    if (lane == 0) atomicAdd(&sR2, r2);

    // ---- Phase C: wait for all bucket producers ----
    if (tid == 0) {
        volatile int* p = &g_ready;
        while (*p < 128) { }
        __threadfence();
    }
    __syncthreads();

    int count = g_cnt[rel];
    if (count > MAXC) count = MAXC;
    const int* bucket = g_bucket + (size_t)rel * MAXC;

    float h2 = 0.f, t2 = 0.f, sq = 0.f;
    const int gr  = lane >> 2;   // 0..7 : rows gr, gr+8 of the m16 tile
    const int tig = lane & 3;    // 0..3 : col pair selector

    // ---- Phase D: per-warp 16-row chunks; fragments loaded straight from gmem ----
    for (int base = wid * 16; base < count; base += 4 * 16) {
        const int ne   = min(16, count - base);
        const bool ok0 = (gr < ne);
        const bool ok1 = (gr + 8 < ne);

        const int ib0 = ok0 ? bucket[base + gr] : 0;
        const int ib1 = ok1 ? bucket[base + gr + 8] : 0;
        const float* T0 = ent_w + (size_t)t_idx[ib0] * DIM;
        const float* T1 = ent_w + (size_t)t_idx[ib1] * DIM;
        const float* H0 = ent_w + (size_t)h_idx[ib0] * DIM;
        const float* H1 = ent_w + (size_t)h_idx[ib1] * DIM;

        // preload all A-fragments (T rows gr / gr+8), split to bf16 hi/lo
        uint32_t ah[8][4], al[8][4];
#pragma unroll
        for (int kt = 0; kt < 8; kt++) {
            const int ka = kt * 16 + 2 * tig;
            float2 t0a = ok0 ? *(const float2*)(T0 + ka)     : make_float2(0.f, 0.f);
            float2 t0b = ok0 ? *(const float2*)(T0 + ka + 8) : make_float2(0.f, 0.f);
            float2 t1a = ok1 ? *(const float2*)(T1 + ka)     : make_float2(0.f, 0.f);
            float2 t1b = ok1 ? *(const float2*)(T1 + ka + 8) : make_float2(0.f, 0.f);
            t2 += t0a.x * t0a.x + t0a.y * t0a.y + t0b.x * t0b.x + t0b.y * t0b.y
                + t1a.x * t1a.x + t1a.y * t1a.y + t1b.x * t1b.x + t1b.y * t1b.y;
            split_u32(t0a.x, t0a.y, ah[kt][0], al[kt][0]);
            split_u32(t1a.x, t1a.y, ah[kt][1], al[kt][1]);
            split_u32(t0b.x, t0b.y, ah[kt][2], al[kt][2]);
            split_u32(t1b.x, t1b.y, ah[kt][3], al[kt][3]);
        }

        // nt-outer: 8 output cols per nt, immediate epilogue, only acc[4] live
        float s0 = 0.f, s1 = 0.f;
#pragma unroll
        for (int nt = 0; nt < 16; nt++) {
            float c0 = 0.f, c1 = 0.f, c2 = 0.f, c3 = 0.f;
            const int n = nt * 8 + gr;
            const char* rh = Rhi + n * KPB;
            const char* rl = Rlo + n * KPB;
#pragma unroll
            for (int kt = 0; kt < 8; kt++) {
                const int kb = kt * 32 + 4 * tig;
                uint32_t bh0 = *(const uint32_t*)(rh + kb);
                uint32_t bh1 = *(const uint32_t*)(rh + kb + 16);
                uint32_t bl0 = *(const uint32_t*)(rl + kb);
                uint32_t bl1 = *(const uint32_t*)(rl + kb + 16);
                mma_bf16(c0, c1, c2, c3, ah[kt][0], ah[kt][1], ah[kt][2], ah[kt][3], bh0, bh1);
                mma_bf16(c0, c1, c2, c3, ah[kt][0], ah[kt][1], ah[kt][2], ah[kt][3], bl0, bl1);
                mma_bf16(c0, c1, c2, c3, al[kt][0], al[kt][1], al[kt][2], al[kt][3], bh0, bh1);
            }
            const int cn = nt * 8 + 2 * tig;
            float2 hA = ok0 ? *(const float2*)(H0 + cn) : make_float2(0.f, 0.f);
            float2 hB = ok1 ? *(const float2*)(H1 + cn) : make_float2(0.f, 0.f);
            h2 += hA.x * hA.x + hA.y * hA.y + hB.x * hB.x + hB.y * hB.y;
            s0 += hA.x * c0 + hA.y * c1;
            s1 += hB.x * c2 + hB.y * c3;
        }

        // reduce over the 4 lanes of each row group (tig dimension)
        s0 += __shfl_xor_sync(0xffffffffu, s0, 1);
        s0 += __shfl_xor_sync(0xffffffffu, s0, 2);
        s1 += __shfl_xor_sync(0xffffffffu, s1, 1);
        s1 += __shfl_xor_sync(0xffffffffu, s1, 2);
        if (tig == 0) {
            if (ok0) {
                out[1 + ib0] = s0;
                float d = s0 - labels[ib0];
                sq += d * d;
            }
            if (ok1) {
                out[1 + ib1] = s1;
                float d = s1 - labels[ib1];
                sq += d * d;
            }
        }
    }

    // ---- Phase E: loss partials + last-block finalize & state reset ----
    h2 = warpSum(h2);
    t2 = warpSum(t2);
    sq = warpSum(sq);
    if (lane == 0) {
        atomicAdd(&sH2, h2);
        atomicAdd(&sT2, t2);
        atomicAdd(&sE2, sq);
    }
    __syncthreads();
    if (tid == 0) {
        atomicAdd(&g_acc[0], sH2);
        atomicAdd(&g_acc[1], sT2);
        atomicAdd(&g_acc[2], sR2 * (float)count);
        atomicAdd(&g_acc[3], sE2);
        __threadfence();
        int old = atomicAdd(&g_done, 1);
        if (old == NREL - 1) sLast = 1;
    }
    __syncthreads();

    if (sLast) {
        for (int i = tid; i < NREL; i += 128) g_cnt[i] = 0;
        if (tid == 0) {
            __threadfence();
            const float invBD  = 1.0f / ((float)BATCH * (float)DIM);
            const float invBDD = 1.0f / ((float)BATCH * (float)DIM * (float)DIM);
            float norms = (g_acc[0] * invBD + g_acc[1] * invBD + g_acc[2] * invBDD)
                        * (1.0f / 3.0f);
            out[0] = g_acc[3] / (float)BATCH + ALPHA * norms;
            g_acc[0] = 0.f; g_acc[1] = 0.f; g_acc[2] = 0.f; g_acc[3] = 0.f;
            g_done  = 0;
            g_ready = 0;
        }
    }
}

extern "C" void kernel_launch(void* const* d_in, const int* in_sizes, int n_in,
                              void* d_out, int out_size)
{
    const int*   h_idx  = (const int*)d_in[0];
    const int*   r_idx  = (const int*)d_in[1];
    const int*   t_idx  = (const int*)d_in[2];
    const float* labels = (const float*)d_in[3];
    const float* ent_w  = (const float*)d_in[4];
    const float* rel_w  = (const float*)d_in[5];
    float*       out    = (float*)d_out;

    cudaFuncSetAttribute(rescal_fused,
                         cudaFuncAttributeMaxDynamicSharedMemorySize, SMEM_TOTAL);

    rescal_fused<<<NREL, 128, SMEM_TOTAL>>>(h_idx, r_idx, t_idx, labels,
                                            ent_w, rel_w, out);
}